// round 15
// baseline (speedup 1.0000x reference)
#include <cuda_runtime.h>
#include <cuda_fp16.h>
#include <math.h>
#include <stdint.h>

// Problem dims (fixed per reference)
#define BATCH   1024
#define IN_DIM  1024
#define HID     4096
#define KX      (IN_DIM + HID)   // 5120
#define G4      (4 * HID)        // 16384
#define OUT_DIM 4096

// ---------------- scratch (no cudaMalloc allowed) ----------------
// Referenced ONLY inside device code (host-side use would get the host shadow).
__device__ __align__(16) __half g_xh[BATCH * KX];
__device__ __align__(16) __half g_wh[(size_t)G4 * KX];
__device__ __align__(16) __half g_wouth[(size_t)OUT_DIM * HID];
__device__ __align__(16) __half g_hth[BATCH * HID];
__device__ float g_gates[(size_t)BATCH * G4];
__device__ float g_logits[(size_t)BATCH * OUT_DIM];

// ---------------- PTX helpers ----------------
__device__ __forceinline__ uint32_t smem_u32(const void* p) {
    uint32_t a;
    asm("{ .reg .u64 t; cvta.to.shared.u64 t, %1; cvt.u32.u64 %0, t; }" : "=r"(a) : "l"(p));
    return a;
}
__device__ __forceinline__ void cp16(uint32_t s, const void* g) {
    asm volatile("cp.async.cg.shared.global [%0], [%1], 16;" :: "r"(s), "l"(g) : "memory");
}
__device__ __forceinline__ void cp_commit() {
    asm volatile("cp.async.commit_group;" ::: "memory");
}
__device__ __forceinline__ void cp_wait1() {
    asm volatile("cp.async.wait_group 1;" ::: "memory");
}
__device__ __forceinline__ void ldsm4(uint32_t* r, uint32_t addr) {
    asm volatile("ldmatrix.sync.aligned.m8n8.x4.shared.b16 {%0,%1,%2,%3}, [%4];"
                 : "=r"(r[0]), "=r"(r[1]), "=r"(r[2]), "=r"(r[3]) : "r"(addr));
}
__device__ __forceinline__ void mma16816(float* d, const uint32_t* a, uint32_t b0, uint32_t b1) {
    asm volatile("mma.sync.aligned.m16n8k16.row.col.f32.f16.f16.f32 "
                 "{%0,%1,%2,%3}, {%4,%5,%6,%7}, {%8,%9}, {%0,%1,%2,%3};"
                 : "+f"(d[0]), "+f"(d[1]), "+f"(d[2]), "+f"(d[3])
                 : "r"(a[0]), "r"(a[1]), "r"(a[2]), "r"(a[3]), "r"(b0), "r"(b1));
}

// ---------------- fp32 -> fp16 converters (vectorized) ----------------
__device__ __forceinline__ void cvt4_store(float4 v, __half* dst) {
    __half2 h0 = __floats2half2_rn(v.x, v.y);
    __half2 h1 = __floats2half2_rn(v.z, v.w);
    uint2 u;
    u.x = *(uint32_t*)&h0;
    u.y = *(uint32_t*)&h1;
    *(uint2*)dst = u;
}

__global__ void convert_x_kernel(const float* __restrict__ i_, const float* __restrict__ h_) {
    const int b = blockIdx.x;
    for (int k4 = threadIdx.x; k4 < KX / 4; k4 += blockDim.x) {
        int k = k4 * 4;
        float4 v = (k < IN_DIM) ? *(const float4*)(i_ + (size_t)b * IN_DIM + k)
                                : *(const float4*)(h_ + (size_t)b * HID + (k - IN_DIM));
        cvt4_store(v, &g_xh[(size_t)b * KX + k]);
    }
}

__global__ void convert_w_kernel(const float* __restrict__ Wf, const float* __restrict__ Wi,
                                 const float* __restrict__ Wc, const float* __restrict__ Wo) {
    const int n = blockIdx.x;                 // stacked weight row (0..16383)
    const int gate = n >> 12;
    const int nl = n & (HID - 1);
    const float* src = (gate == 0) ? Wf : (gate == 1) ? Wi : (gate == 2) ? Wc : Wo;
    const float* row = src + (size_t)nl * KX;
    __half* dst = g_wh + (size_t)n * KX;
    for (int k4 = threadIdx.x; k4 < KX / 4; k4 += blockDim.x) {
        int k = k4 * 4;
        cvt4_store(*(const float4*)(row + k), &dst[k]);
    }
}

__global__ void convert_wout_kernel(const float* __restrict__ W) {
    const int n = blockIdx.x;
    const float* row = W + (size_t)n * HID;
    __half* dst = g_wouth + (size_t)n * HID;
    for (int k4 = threadIdx.x; k4 < HID / 4; k4 += blockDim.x) {
        int k = k4 * 4;
        cvt4_store(*(const float4*)(row + k), &dst[k]);
    }
}

// ---------------- single-pass fp16 GEMM: C[M,N] = A[M,K] @ W[N,K]^T ----------------
// fp32 accum via mma.sync m16n8k16.f16. CTA 128M x 128N, 4 warps (2Mx2N, 64x64 each),
// k-step 64, 3-stage cp.async pipeline (distance 2), 2 CTAs/SM.
// NEW: fragment double-buffering — kk+1's ldmatrix issue under kk's MMA burst,
// hiding LDSM latency for 3 of 4 kk-steps per iteration.
#define WLD   72                        // smem leading dim (elements); 144 B rows
#define A_EL  (128 * WLD)               // one matrix buffer (A or W)
#define STEL  (2 * A_EL)                // per stage: [A][W] = 18432 el = 36864 B

template <int PASS_ID>
__global__ __launch_bounds__(128, 2)
void gemm_mma_kernel()
{
    constexpr int N = (PASS_ID == 0) ? G4 : OUT_DIM;
    constexpr int K = (PASS_ID == 0) ? KX : HID;
    const __half* __restrict__ A = (PASS_ID == 0) ? g_xh : g_hth;
    const __half* __restrict__ W = (PASS_ID == 0) ? g_wh : g_wouth;
    float* __restrict__ C = (PASS_ID == 0) ? g_gates : g_logits;

    extern __shared__ __align__(16) __half smem[];   // 3 * STEL elements
    const uint32_t sbase = smem_u32(smem);

    const int tid  = threadIdx.x;
    const int lane = tid & 31;
    const int wid  = tid >> 5;
    const int warp_m = wid & 1;    // 2 warps over M, 64 rows each
    const int warp_n = wid >> 1;   // 2 warps over N, 64 cols each

    const int m0 = blockIdx.x * 128;
    const int n0 = blockIdx.y * 128;
    const int niter = K / 64;

    // ---- producer mapping: row has 8x16B chunks; thread -> row rP(+16p), chunk cP
    const int rP = tid >> 3, cP = tid & 7;   // rP 0..15
    const __half* baseA = A + (size_t)(m0 + rP) * K + cP * 8;
    const __half* baseW = W + (size_t)(n0 + rP) * K + cP * 8;
    const uint32_t sOffBase = (uint32_t)(rP * WLD + cP * 8) * 2;

    auto issue_stage = [&](int stage, int it) {
        const uint32_t st = sbase + (uint32_t)(stage * STEL) * 2;
        const int k0 = it * 64;
#pragma unroll
        for (int p = 0; p < 8; p++) {
            const uint32_t so = sOffBase + (uint32_t)(p * 16 * WLD) * 2;
            cp16(st + so,              baseA + (size_t)(p * 16) * K + k0);
            cp16(st + A_EL * 2 + so,   baseW + (size_t)(p * 16) * K + k0);
        }
    };

    // ---- consumer ldmatrix lane addressing (byte offsets within a matrix buffer)
    const uint32_t aLane = (uint32_t)(((warp_m * 64) + (lane & 7) + ((lane >> 3) & 1) * 8) * WLD
                                      + (lane >> 4) * 8) * 2;
    const uint32_t bLane = (uint32_t)(((warp_n * 64) + (lane & 7) + (lane >> 4) * 8) * WLD
                                      + ((lane >> 3) & 1) * 8) * 2;

    float acc[4][8][4];
#pragma unroll
    for (int mt = 0; mt < 4; mt++)
#pragma unroll
        for (int j = 0; j < 8; j++)
#pragma unroll
            for (int r = 0; r < 4; r++) acc[mt][j][r] = 0.f;

    // fragment double buffers
    uint32_t af[2][4][4], bf[2][16];

    auto load_frags = [&](int buf, uint32_t sA, uint32_t sW, int kk) {
        const uint32_t kb = (uint32_t)(kk * 32);
#pragma unroll
        for (int mt = 0; mt < 4; ++mt)
            ldsm4(af[buf][mt], sA + (uint32_t)(mt * 16 * WLD) * 2 + aLane + kb);
#pragma unroll
        for (int np = 0; np < 4; ++np)
            ldsm4(&bf[buf][4 * np], sW + (uint32_t)(np * 16 * WLD) * 2 + bLane + kb);
    };

    // prologue: stages 0 and 1 in flight
    issue_stage(0, 0); cp_commit();
    issue_stage(1, 1); cp_commit();

    int stage = 0;
    for (int it = 0; it < niter; ++it) {
        cp_wait1();        // group for `it` done (group it+1 may be pending)
        __syncthreads();   // all warps past iter it-1; stage (it+2)%3 has no readers

        if (it + 2 < niter) issue_stage((stage + 2) % 3, it + 2);
        cp_commit();       // one group per iteration (may be empty at tail)

        const uint32_t sA = sbase + (uint32_t)(stage * STEL) * 2;
        const uint32_t sW = sA + A_EL * 2;

        load_frags(0, sA, sW, 0);          // kk=0 fragments (exposed once per iter)
#pragma unroll
        for (int kk = 0; kk < 4; ++kk) {
            const int cur = kk & 1;
            if (kk < 3) load_frags(cur ^ 1, sA, sW, kk + 1);  // prefetch under MMAs
#pragma unroll
            for (int mt = 0; mt < 4; ++mt)
#pragma unroll
                for (int j = 0; j < 8; ++j)
                    mma16816(acc[mt][j], af[cur][mt], bf[cur][2 * j], bf[cur][2 * j + 1]);
        }
        stage = (stage + 1) % 3;
    }

    // ---- epilogue: m16n8 frag -> d0,d1 @(row,col), d2,d3 @(row+8,col)
    const int erow = lane >> 2;
    const int ecol = (lane & 3) * 2;
    float* Cw = C + (size_t)(m0 + warp_m * 64) * N + n0 + warp_n * 64;
#pragma unroll
    for (int mt = 0; mt < 4; ++mt)
#pragma unroll
        for (int j = 0; j < 8; ++j) {
            float* p0 = Cw + (size_t)(mt * 16 + erow) * N + j * 8 + ecol;
            *(float2*)p0                   = make_float2(acc[mt][j][0], acc[mt][j][1]);
            *(float2*)(p0 + (size_t)8 * N) = make_float2(acc[mt][j][2], acc[mt][j][3]);
        }
}

// ---------------- LSTM elementwise ----------------
__global__ void lstm_act_kernel(const float* __restrict__ cin,
                                const float* __restrict__ bf, const float* __restrict__ bi,
                                const float* __restrict__ bc, const float* __restrict__ bo,
                                float* __restrict__ out_it, float* __restrict__ out_ht,
                                float* __restrict__ out_ct)
{
    int idx = blockIdx.x * blockDim.x + threadIdx.x;
    if (idx >= BATCH * HID) return;
    int b = idx / HID;
    int j = idx - b * HID;
    const float* g = g_gates + (size_t)b * G4;
    float fp = g[j]           + bf[j];
    float ip = g[HID + j]     + bi[j];
    float cp = g[2 * HID + j] + bc[j];
    float op = g[3 * HID + j] + bo[j];
    float ft = 1.f / (1.f + __expf(-fp));
    float it = 1.f / (1.f + __expf(-ip));
    float cb = tanhf(cp);
    float ct = ft * cin[idx] + it * cb;
    float ot = 1.f / (1.f + __expf(-op));
    float ht = ot * tanhf(ct);
    out_it[idx] = it;
    out_ht[idx] = ht;
    out_ct[idx] = ct;
    g_hth[idx] = __float2half(ht);
}

// ---------------- log_softmax ----------------
__global__ void logsoftmax_kernel(const float* __restrict__ bout,
                                  float* __restrict__ out)
{
    const int row = blockIdx.x;
    const float* x = g_logits + (size_t)row * OUT_DIM;
    float* y = out + (size_t)row * OUT_DIM;
    __shared__ float red[256];
    const int tid = threadIdx.x;

    float mx = -INFINITY;
    for (int j = tid; j < OUT_DIM; j += 256) mx = fmaxf(mx, x[j] + bout[j]);
    red[tid] = mx; __syncthreads();
    for (int s = 128; s > 0; s >>= 1) {
        if (tid < s) red[tid] = fmaxf(red[tid], red[tid + s]);
        __syncthreads();
    }
    mx = red[0];
    __syncthreads();

    float sum = 0.f;
    for (int j = tid; j < OUT_DIM; j += 256) sum += __expf(x[j] + bout[j] - mx);
    red[tid] = sum; __syncthreads();
    for (int s = 128; s > 0; s >>= 1) {
        if (tid < s) red[tid] += red[tid + s];
        __syncthreads();
    }
    float lse = mx + logf(red[0]);

    for (int j = tid; j < OUT_DIM; j += 256) y[j] = x[j] + bout[j] - lse;
}

// ---------------- launch ----------------
extern "C" void kernel_launch(void* const* d_in, const int* in_sizes, int n_in,
                              void* d_out, int out_size)
{
    const float* in_i  = (const float*)d_in[0];
    const float* in_h  = (const float*)d_in[1];
    const float* in_c  = (const float*)d_in[2];
    const float* Wf    = (const float*)d_in[3];
    const float* bf_   = (const float*)d_in[4];
    const float* Wi    = (const float*)d_in[5];
    const float* bi_   = (const float*)d_in[6];
    const float* Wc    = (const float*)d_in[7];
    const float* bc_   = (const float*)d_in[8];
    const float* Wo    = (const float*)d_in[9];
    const float* bo_   = (const float*)d_in[10];
    const float* Wout  = (const float*)d_in[11];
    const float* bout  = (const float*)d_in[12];

    float* out    = (float*)d_out;
    float* out_it = out;
    float* out_ht = out + (size_t)BATCH * HID;
    float* out_ct = out + 2 * (size_t)BATCH * HID;
    float* out_ls = out + 3 * (size_t)BATCH * HID;

    const int SMEM_DYN = 3 * STEL * 2;   // 3 stages * 36864 B = 110592
    cudaFuncSetAttribute(gemm_mma_kernel<0>,
                         cudaFuncAttributeMaxDynamicSharedMemorySize, SMEM_DYN);
    cudaFuncSetAttribute(gemm_mma_kernel<1>,
                         cudaFuncAttributeMaxDynamicSharedMemorySize, SMEM_DYN);

    // 1) fp32 -> fp16 conversions (vectorized)
    convert_x_kernel<<<BATCH, 256>>>(in_i, in_h);
    convert_w_kernel<<<G4, 256>>>(Wf, Wi, Wc, Wo);
    convert_wout_kernel<<<OUT_DIM, 256>>>(Wout);

    // 2) gates = x @ [Wf;Wi;Wc;Wo]^T  (single-pass fp16, fp32 accum)
    {
        dim3 grid(BATCH / 128, G4 / 128);
        gemm_mma_kernel<0><<<grid, 128, SMEM_DYN>>>();
    }

    // 3) elementwise LSTM cell -> it, ht, ct (+ ht fp16)
    {
        int total = BATCH * HID;
        lstm_act_kernel<<<(total + 255) / 256, 256>>>(in_c, bf_, bi_, bc_, bo_,
                                                      out_it, out_ht, out_ct);
    }

    // 4) logits = ht @ Wout^T
    {
        dim3 grid(BATCH / 128, OUT_DIM / 128);
        gemm_mma_kernel<1><<<grid, 128, SMEM_DYN>>>();
    }

    // 5) log_softmax(logits + bout) -> out
    logsoftmax_kernel<<<BATCH, 256>>>(bout, out_ls);
}

// round 16
// speedup vs baseline: 1.1338x; 1.1338x over previous
#include <cuda_runtime.h>
#include <cuda_fp16.h>
#include <math.h>
#include <stdint.h>

// Problem dims (fixed per reference)
#define BATCH   1024
#define IN_DIM  1024
#define HID     4096
#define KX      (IN_DIM + HID)   // 5120
#define G4      (4 * HID)        // 16384
#define OUT_DIM 4096

// ---------------- scratch (no cudaMalloc allowed) ----------------
// Referenced ONLY inside device code (host-side use would get the host shadow).
__device__ __align__(16) __half g_xh[BATCH * KX];
__device__ __align__(16) __half g_wh[(size_t)G4 * KX];
__device__ __align__(16) __half g_wouth[(size_t)OUT_DIM * HID];
__device__ __align__(16) __half g_hth[BATCH * HID];
__device__ float g_gates[(size_t)BATCH * G4];
__device__ float g_logits[(size_t)BATCH * OUT_DIM];

// ---------------- PTX helpers ----------------
__device__ __forceinline__ uint32_t smem_u32(const void* p) {
    uint32_t a;
    asm("{ .reg .u64 t; cvta.to.shared.u64 t, %1; cvt.u32.u64 %0, t; }" : "=r"(a) : "l"(p));
    return a;
}
__device__ __forceinline__ void cp16(uint32_t s, const void* g) {
    asm volatile("cp.async.cg.shared.global [%0], [%1], 16;" :: "r"(s), "l"(g) : "memory");
}
__device__ __forceinline__ void cp_commit() {
    asm volatile("cp.async.commit_group;" ::: "memory");
}
__device__ __forceinline__ void cp_wait0() {
    asm volatile("cp.async.wait_group 0;" ::: "memory");
}
__device__ __forceinline__ void ldsm4(uint32_t* r, uint32_t addr) {
    asm volatile("ldmatrix.sync.aligned.m8n8.x4.shared.b16 {%0,%1,%2,%3}, [%4];"
                 : "=r"(r[0]), "=r"(r[1]), "=r"(r[2]), "=r"(r[3]) : "r"(addr));
}
__device__ __forceinline__ void mma16816(float* d, const uint32_t* a, uint32_t b0, uint32_t b1) {
    asm volatile("mma.sync.aligned.m16n8k16.row.col.f32.f16.f16.f32 "
                 "{%0,%1,%2,%3}, {%4,%5,%6,%7}, {%8,%9}, {%0,%1,%2,%3};"
                 : "+f"(d[0]), "+f"(d[1]), "+f"(d[2]), "+f"(d[3])
                 : "r"(a[0]), "r"(a[1]), "r"(a[2]), "r"(a[3]), "r"(b0), "r"(b1));
}

// ---------------- fp32 -> fp16 converters (vectorized) ----------------
__device__ __forceinline__ void cvt4_store(float4 v, __half* dst) {
    __half2 h0 = __floats2half2_rn(v.x, v.y);
    __half2 h1 = __floats2half2_rn(v.z, v.w);
    uint2 u;
    u.x = *(uint32_t*)&h0;
    u.y = *(uint32_t*)&h1;
    *(uint2*)dst = u;
}

__global__ void convert_x_kernel(const float* __restrict__ i_, const float* __restrict__ h_) {
    const int b = blockIdx.x;
    for (int k4 = threadIdx.x; k4 < KX / 4; k4 += blockDim.x) {
        int k = k4 * 4;
        float4 v = (k < IN_DIM) ? *(const float4*)(i_ + (size_t)b * IN_DIM + k)
                                : *(const float4*)(h_ + (size_t)b * HID + (k - IN_DIM));
        cvt4_store(v, &g_xh[(size_t)b * KX + k]);
    }
}

__global__ void convert_w_kernel(const float* __restrict__ Wf, const float* __restrict__ Wi,
                                 const float* __restrict__ Wc, const float* __restrict__ Wo) {
    const int n = blockIdx.x;                 // stacked weight row (0..16383)
    const int gate = n >> 12;
    const int nl = n & (HID - 1);
    const float* src = (gate == 0) ? Wf : (gate == 1) ? Wi : (gate == 2) ? Wc : Wo;
    const float* row = src + (size_t)nl * KX;
    __half* dst = g_wh + (size_t)n * KX;
    for (int k4 = threadIdx.x; k4 < KX / 4; k4 += blockDim.x) {
        int k = k4 * 4;
        cvt4_store(*(const float4*)(row + k), &dst[k]);
    }
}

__global__ void convert_wout_kernel(const float* __restrict__ W) {
    const int n = blockIdx.x;
    const float* row = W + (size_t)n * HID;
    __half* dst = g_wouth + (size_t)n * HID;
    for (int k4 = threadIdx.x; k4 < HID / 4; k4 += blockDim.x) {
        int k = k4 * 4;
        cvt4_store(*(const float4*)(row + k), &dst[k]);
    }
}

// ---------------- single-pass fp16 GEMM: C[M,N] = A[M,K] @ W[N,K]^T ----------------
// fp32 accum via mma.sync m16n8k16.f16. CTA 64M x 128N, 64 threads = 2 warps
// (1M x 2N, 64x64 per warp — proven body). k-step 64, 2-stage cp.async pipeline,
// 4 CTAs/SM: four fully independent barrier/cp.async domains per SM so the two
// warps sharing each SMSP never stall in lockstep.
#define WLD   72                        // smem leading dim (elements); 144 B rows
#define A_EL  (64 * WLD)                // A buffer: 64 rows
#define W_EL  (128 * WLD)               // W buffer: 128 rows
#define STEL  (A_EL + W_EL)             // per stage: 13824 el = 27648 B

template <int PASS_ID>
__global__ __launch_bounds__(64, 4)
void gemm_mma_kernel()
{
    constexpr int N = (PASS_ID == 0) ? G4 : OUT_DIM;
    constexpr int K = (PASS_ID == 0) ? KX : HID;
    const __half* __restrict__ A = (PASS_ID == 0) ? g_xh : g_hth;
    const __half* __restrict__ W = (PASS_ID == 0) ? g_wh : g_wouth;
    float* __restrict__ C = (PASS_ID == 0) ? g_gates : g_logits;

    extern __shared__ __align__(16) __half smem[];   // 2 * STEL elements
    const uint32_t sbase = smem_u32(smem);

    const int tid  = threadIdx.x;
    const int lane = tid & 31;
    const int warp_n = tid >> 5;   // 2 warps over N, 64 cols each

    const int m0 = blockIdx.x * 64;
    const int n0 = blockIdx.y * 128;
    const int niter = K / 64;

    // ---- producer mapping: row = 8 x 16B chunks; thread -> row rP(+8p), chunk cP
    const int rP = tid >> 3, cP = tid & 7;   // rP 0..7
    const __half* baseA = A + (size_t)(m0 + rP) * K + cP * 8;
    const __half* baseW = W + (size_t)(n0 + rP) * K + cP * 8;
    const uint32_t sOffBase = (uint32_t)(rP * WLD + cP * 8) * 2;

    auto issue_stage = [&](int stage, int it) {
        const uint32_t st = sbase + (uint32_t)(stage * STEL) * 2;
        const int k0 = it * 64;
#pragma unroll
        for (int p = 0; p < 8; p++) {    // A: 64 rows
            const uint32_t so = sOffBase + (uint32_t)(p * 8 * WLD) * 2;
            cp16(st + so, baseA + (size_t)(p * 8) * K + k0);
        }
#pragma unroll
        for (int p = 0; p < 16; p++) {   // W: 128 rows
            const uint32_t so = sOffBase + (uint32_t)(p * 8 * WLD) * 2;
            cp16(st + A_EL * 2 + so, baseW + (size_t)(p * 8) * K + k0);
        }
    };

    // ---- consumer ldmatrix lane addressing (byte offsets within a matrix buffer)
    const uint32_t aLane = (uint32_t)(((lane & 7) + ((lane >> 3) & 1) * 8) * WLD
                                      + (lane >> 4) * 8) * 2;
    const uint32_t bLane = (uint32_t)(((warp_n * 64) + (lane & 7) + (lane >> 4) * 8) * WLD
                                      + ((lane >> 3) & 1) * 8) * 2;

    float acc[4][8][4];
#pragma unroll
    for (int mt = 0; mt < 4; mt++)
#pragma unroll
        for (int j = 0; j < 8; j++)
#pragma unroll
            for (int r = 0; r < 4; r++) acc[mt][j][r] = 0.f;

    // prologue: stage 0 in flight
    issue_stage(0, 0); cp_commit();

    int stage = 0;
    for (int it = 0; it < niter; ++it) {
        cp_wait0();        // stage for `it` loaded
        __syncthreads();   // both warps past iter it-1 compute (freed stage^1)

        if (it + 1 < niter) issue_stage(stage ^ 1, it + 1);
        cp_commit();       // one group per iteration (may be empty at tail)

        const uint32_t sA = sbase + (uint32_t)(stage * STEL) * 2;
        const uint32_t sW = sA + A_EL * 2;

#pragma unroll
        for (int kk = 0; kk < 4; ++kk) {
            const uint32_t kb = (uint32_t)(kk * 32);   // 16 elements = 32 bytes

            uint32_t af[4][4], bf[16];
#pragma unroll
            for (int mt = 0; mt < 4; ++mt)
                ldsm4(af[mt], sA + (uint32_t)(mt * 16 * WLD) * 2 + aLane + kb);
#pragma unroll
            for (int np = 0; np < 4; ++np)
                ldsm4(&bf[4 * np], sW + (uint32_t)(np * 16 * WLD) * 2 + bLane + kb);

#pragma unroll
            for (int mt = 0; mt < 4; ++mt)
#pragma unroll
                for (int j = 0; j < 8; ++j)
                    mma16816(acc[mt][j], af[mt], bf[2 * j], bf[2 * j + 1]);
        }
        stage ^= 1;
    }

    // ---- epilogue: m16n8 frag -> d0,d1 @(row,col), d2,d3 @(row+8,col)
    const int erow = lane >> 2;
    const int ecol = (lane & 3) * 2;
    float* Cw = C + (size_t)m0 * N + n0 + warp_n * 64;
#pragma unroll
    for (int mt = 0; mt < 4; ++mt)
#pragma unroll
        for (int j = 0; j < 8; ++j) {
            float* p0 = Cw + (size_t)(mt * 16 + erow) * N + j * 8 + ecol;
            *(float2*)p0                   = make_float2(acc[mt][j][0], acc[mt][j][1]);
            *(float2*)(p0 + (size_t)8 * N) = make_float2(acc[mt][j][2], acc[mt][j][3]);
        }
}

// ---------------- LSTM elementwise ----------------
__global__ void lstm_act_kernel(const float* __restrict__ cin,
                                const float* __restrict__ bf, const float* __restrict__ bi,
                                const float* __restrict__ bc, const float* __restrict__ bo,
                                float* __restrict__ out_it, float* __restrict__ out_ht,
                                float* __restrict__ out_ct)
{
    int idx = blockIdx.x * blockDim.x + threadIdx.x;
    if (idx >= BATCH * HID) return;
    int b = idx / HID;
    int j = idx - b * HID;
    const float* g = g_gates + (size_t)b * G4;
    float fp = g[j]           + bf[j];
    float ip = g[HID + j]     + bi[j];
    float cp = g[2 * HID + j] + bc[j];
    float op = g[3 * HID + j] + bo[j];
    float ft = 1.f / (1.f + __expf(-fp));
    float it = 1.f / (1.f + __expf(-ip));
    float cb = tanhf(cp);
    float ct = ft * cin[idx] + it * cb;
    float ot = 1.f / (1.f + __expf(-op));
    float ht = ot * tanhf(ct);
    out_it[idx] = it;
    out_ht[idx] = ht;
    out_ct[idx] = ct;
    g_hth[idx] = __float2half(ht);
}

// ---------------- log_softmax ----------------
__global__ void logsoftmax_kernel(const float* __restrict__ bout,
                                  float* __restrict__ out)
{
    const int row = blockIdx.x;
    const float* x = g_logits + (size_t)row * OUT_DIM;
    float* y = out + (size_t)row * OUT_DIM;
    __shared__ float red[256];
    const int tid = threadIdx.x;

    float mx = -INFINITY;
    for (int j = tid; j < OUT_DIM; j += 256) mx = fmaxf(mx, x[j] + bout[j]);
    red[tid] = mx; __syncthreads();
    for (int s = 128; s > 0; s >>= 1) {
        if (tid < s) red[tid] = fmaxf(red[tid], red[tid + s]);
        __syncthreads();
    }
    mx = red[0];
    __syncthreads();

    float sum = 0.f;
    for (int j = tid; j < OUT_DIM; j += 256) sum += __expf(x[j] + bout[j] - mx);
    red[tid] = sum; __syncthreads();
    for (int s = 128; s > 0; s >>= 1) {
        if (tid < s) red[tid] += red[tid + s];
        __syncthreads();
    }
    float lse = mx + logf(red[0]);

    for (int j = tid; j < OUT_DIM; j += 256) y[j] = x[j] + bout[j] - lse;
}

// ---------------- launch ----------------
extern "C" void kernel_launch(void* const* d_in, const int* in_sizes, int n_in,
                              void* d_out, int out_size)
{
    const float* in_i  = (const float*)d_in[0];
    const float* in_h  = (const float*)d_in[1];
    const float* in_c  = (const float*)d_in[2];
    const float* Wf    = (const float*)d_in[3];
    const float* bf_   = (const float*)d_in[4];
    const float* Wi    = (const float*)d_in[5];
    const float* bi_   = (const float*)d_in[6];
    const float* Wc    = (const float*)d_in[7];
    const float* bc_   = (const float*)d_in[8];
    const float* Wo    = (const float*)d_in[9];
    const float* bo_   = (const float*)d_in[10];
    const float* Wout  = (const float*)d_in[11];
    const float* bout  = (const float*)d_in[12];

    float* out    = (float*)d_out;
    float* out_it = out;
    float* out_ht = out + (size_t)BATCH * HID;
    float* out_ct = out + 2 * (size_t)BATCH * HID;
    float* out_ls = out + 3 * (size_t)BATCH * HID;

    const int SMEM_DYN = 2 * STEL * 2;   // 2 stages * 27648 B = 55296
    cudaFuncSetAttribute(gemm_mma_kernel<0>,
                         cudaFuncAttributeMaxDynamicSharedMemorySize, SMEM_DYN);
    cudaFuncSetAttribute(gemm_mma_kernel<1>,
                         cudaFuncAttributeMaxDynamicSharedMemorySize, SMEM_DYN);

    // 1) fp32 -> fp16 conversions (vectorized)
    convert_x_kernel<<<BATCH, 256>>>(in_i, in_h);
    convert_w_kernel<<<G4, 256>>>(Wf, Wi, Wc, Wo);
    convert_wout_kernel<<<OUT_DIM, 256>>>(Wout);

    // 2) gates = x @ [Wf;Wi;Wc;Wo]^T  (single-pass fp16, fp32 accum)
    {
        dim3 grid(BATCH / 64, G4 / 128);
        gemm_mma_kernel<0><<<grid, 64, SMEM_DYN>>>();
    }

    // 3) elementwise LSTM cell -> it, ht, ct (+ ht fp16)
    {
        int total = BATCH * HID;
        lstm_act_kernel<<<(total + 255) / 256, 256>>>(in_c, bf_, bi_, bc_, bo_,
                                                      out_it, out_ht, out_ct);
    }

    // 4) logits = ht @ Wout^T
    {
        dim3 grid(BATCH / 64, OUT_DIM / 128);
        gemm_mma_kernel<1><<<grid, 64, SMEM_DYN>>>();
    }

    // 5) log_softmax(logits + bout) -> out
    logsoftmax_kernel<<<BATCH, 256>>>(bout, out_ls);
}